// round 7
// baseline (speedup 1.0000x reference)
#include <cuda_runtime.h>
#include <cuda_fp16.h>
#include <math.h>
#include <stdint.h>

// Problem dims (fixed)
#define KENT    8
#define BENT    4096
#define MDIM    4096
#define HIN     512
#define HENC    256
#define HCORE   512
#define HCTX    256
#define HSTATE  512
#define NPAIR   (BENT * (KENT - 1))   // 28672
#define HTOT    (HENC + HCTX + HIN)   // 1024

// ---- fp16 scratch (no allocation allowed) ----
__device__ __half g_inh[(size_t)BENT * MDIM];
__device__ __half g_sth[BENT * HSTATE];
__device__ __half g_Winh[MDIM * HIN];
__device__ __half g_Wench[HSTATE * HENC];
__device__ __half g_Wcoreh[2 * HENC * HCORE];
__device__ __half g_Wctxh[HCORE * HCTX];
__device__ __half g_Wrech[HTOT * HSTATE];
__device__ __half g_Wouth[HSTATE * MDIM];
__device__ __half g_Xh[BENT * HIN];
__device__ __half g_S1h[BENT * HENC];
__device__ __half g_coreh[(size_t)NPAIR * HCORE];
__device__ __half g_ctxh[(size_t)NPAIR * HCTX];
__device__ float  g_att[NPAIR];
__device__ __half g_Eh[BENT * HCTX];
__device__ __half g_Th[BENT * HTOT];
__device__ __half g_NSh[BENT * HSTATE];

template<int ACT>
__device__ __forceinline__ float actf(float v) {
    if (ACT == 1) return fmaxf(v, 0.0f);                  // relu
    if (ACT == 2) return 1.0f / (1.0f + expf(-v));        // sigmoid
    if (ACT == 3) return v > 0.0f ? v : expm1f(v);        // elu
    return v;
}

// fp32 -> fp16 bulk convert, 8 elems/thread
__global__ void __launch_bounds__(256)
cvt_k(const float* __restrict__ s, __half* __restrict__ d, int n)
{
    int i = (blockIdx.x * blockDim.x + threadIdx.x) * 8;
    if (i >= n) return;
    float4 a = *(const float4*)(s + i);
    float4 b = *(const float4*)(s + i + 4);
    __half2 h0 = __floats2half2_rn(a.x, a.y);
    __half2 h1 = __floats2half2_rn(a.z, a.w);
    __half2 h2 = __floats2half2_rn(b.x, b.y);
    __half2 h3 = __floats2half2_rn(b.z, b.w);
    uint4 o;
    o.x = *(uint32_t*)&h0; o.y = *(uint32_t*)&h1;
    o.z = *(uint32_t*)&h2; o.w = *(uint32_t*)&h3;
    *(uint4*)(d + i) = o;
}

#define STAGES 4
#define ASTR 80                       // A row: 32 fp16 + 16B pad
#define BSTR 272                      // B row: 128 fp16 + 16B pad
#define BBUF (32 * BSTR)              // 8704

__device__ __forceinline__ void cp16(uint32_t dst, const void* src) {
    asm volatile("cp.async.cg.shared.global [%0], [%1], 16;" :: "r"(dst), "l"(src));
}

// fp16 tensor-core GEMM, cp.async 4-stage pipeline.
// CTA tile BM x 128 (BM=128: 256 thr, 8 warps 2x4; BM=256: 512 thr, 16 warps 4x4).
// Warp tile fixed 64x32 (m16n8k16), fp32 accum — proven no-spill shape.
// MODE 0: normal A. MODE 1: pair-gathered A from S1h (K = 2*HENC).
// WOUT 0: fp16 C. 1: fp32 C. 2: both.
template<int ACT, int MODE, int WOUT, int BM>
__global__ void __launch_bounds__(BM * 2)
hgemm(const __half* __restrict__ A, const __half* __restrict__ B,
      const float* __restrict__ bias, __half* __restrict__ Ch,
      float* __restrict__ Cf, int N, int K)
{
    constexpr int T    = BM * 2;              // threads
    constexpr int ABUF = BM * ASTR;
    constexpr int STGB = ABUF + BBUF;
    constexpr int BCPB = 512 / T;             // B cp16 per thread (2 or 1)

    extern __shared__ char sm[];
    const uint32_t smb = (uint32_t)__cvta_generic_to_shared(sm);

    const int tid  = threadIdx.x;
    const int warp = tid >> 5;
    const int lane = tid & 31;
    const int row0 = blockIdx.y * BM;
    const int col0 = blockIdx.x * 128;

    const int wm = warp >> 2, wn = warp & 3;  // wm 0..(BM/64-1), wn 0..3
    const int m_base = wm * 64, n_base = wn * 32;
    const int grp = lane >> 2, tg = lane & 3;

    // ldmatrix lane offsets (proven layout)
    const int a_row = (lane & 7) + ((lane >> 3) & 1) * 8;
    const int a_kh  = (lane >> 4) * 8;
    const uint32_t aLane = (uint32_t)((m_base + a_row) * ASTR + a_kh * 2);
    const int b_k  = (lane & 7) + ((lane >> 3) & 1) * 8;
    const int b_nh = (lane >> 4) * 8;
    const uint32_t bLane = (uint32_t)(b_k * BSTR + (n_base + b_nh) * 2);

    // ---- cp.async loader assignments ----
    // A: BM rows x 64B; 2 threads/row, 2x16B each.
    const int arow = tid >> 1;
    const int ak16 = (tid & 1) * 16;
    const uint32_t aoff = (uint32_t)(arow * ASTR + ak16 * 2);
    size_t rcs = 0, rfs = 0;
    const __half* aBase = nullptr;
    if (MODE == 0) {
        aBase = A + (size_t)(row0 + arow) * K + ak16;
    } else {
        int p = row0 + arow;
        int b_ = p / 56, rem = p % 56;
        int ii = rem / 7, jj = rem % 7;
        int j = jj + (jj >= ii ? 1 : 0);
        rcs = (size_t)(b_ * KENT + j) * HENC;
        rfs = (size_t)(b_ * KENT + ii) * HENC;
    }
    // B: 32 rows x 256B. T=256: 8 thr/row x 32B; T=512: 16 thr/row x 16B.
    const int brow = (BCPB == 2) ? (tid >> 3) : (tid >> 4);
    const int bo16 = (BCPB == 2) ? ((tid & 7) * 16) : ((tid & 15) * 8);
    const uint32_t boff = (uint32_t)(brow * BSTR + bo16 * 2);
    const __half* bBase = B + (size_t)brow * N + col0 + bo16;

    auto issue_stage = [&](int s, int kg) {
        uint32_t ab = smb + (uint32_t)s * STGB;
        uint32_t bb = ab + ABUF;
        const __half* asrc;
        if (MODE == 0) {
            asrc = aBase + kg;
        } else {
            int kk = kg + ak16;
            asrc = (kk < HENC) ? (A + rcs + kk) : (A + rfs + (kk - HENC));
        }
        cp16(ab + aoff, asrc);
        cp16(ab + aoff + 16, asrc + 8);
        const __half* bsrc = bBase + (size_t)kg * N;
        cp16(bb + boff, bsrc);
        if (BCPB == 2) cp16(bb + boff + 16, bsrc + 8);
    };

    float acc[4][4][4];
#pragma unroll
    for (int mt = 0; mt < 4; mt++)
#pragma unroll
        for (int nt = 0; nt < 4; nt++)
#pragma unroll
            for (int c = 0; c < 4; c++) acc[mt][nt][c] = 0.0f;

    const int nk = K >> 5;

#pragma unroll
    for (int s = 0; s < STAGES - 1; s++) {
        if (s < nk) issue_stage(s, s << 5);
        asm volatile("cp.async.commit_group;" ::: "memory");
    }

    for (int it = 0; it < nk; ++it) {
        asm volatile("cp.async.wait_group %0;" :: "n"(STAGES - 2) : "memory");
        __syncthreads();
        const int nxt = it + STAGES - 1;
        if (nxt < nk) issue_stage(nxt & (STAGES - 1), nxt << 5);
        asm volatile("cp.async.commit_group;" ::: "memory");

        const uint32_t ab = smb + (uint32_t)(it & (STAGES - 1)) * STGB + aLane;
        const uint32_t bb = smb + (uint32_t)(it & (STAGES - 1)) * STGB + ABUF + bLane;
#pragma unroll
        for (int ks = 0; ks < 2; ks++) {
            uint32_t af[4][4];
#pragma unroll
            for (int mt = 0; mt < 4; mt++) {
                uint32_t addr = ab + mt * (16 * ASTR) + ks * 32;
                asm volatile("ldmatrix.sync.aligned.m8n8.x4.shared.b16 {%0,%1,%2,%3}, [%4];"
                             : "=r"(af[mt][0]), "=r"(af[mt][1]),
                               "=r"(af[mt][2]), "=r"(af[mt][3])
                             : "r"(addr));
            }
            uint32_t bf[4][2];
#pragma unroll
            for (int nl = 0; nl < 2; nl++) {
                uint32_t addr = bb + nl * 32 + ks * (16 * BSTR);
                asm volatile("ldmatrix.sync.aligned.m8n8.x4.trans.shared.b16 {%0,%1,%2,%3}, [%4];"
                             : "=r"(bf[nl*2][0]), "=r"(bf[nl*2][1]),
                               "=r"(bf[nl*2+1][0]), "=r"(bf[nl*2+1][1])
                             : "r"(addr));
            }
#pragma unroll
            for (int mt = 0; mt < 4; mt++) {
#pragma unroll
                for (int nt = 0; nt < 4; nt++) {
                    asm("mma.sync.aligned.m16n8k16.row.col.f32.f16.f16.f32 "
                        "{%0,%1,%2,%3}, {%4,%5,%6,%7}, {%8,%9}, {%0,%1,%2,%3};"
                        : "+f"(acc[mt][nt][0]), "+f"(acc[mt][nt][1]),
                          "+f"(acc[mt][nt][2]), "+f"(acc[mt][nt][3])
                        : "r"(af[mt][0]), "r"(af[mt][1]), "r"(af[mt][2]), "r"(af[mt][3]),
                          "r"(bf[nt][0]), "r"(bf[nt][1]));
                }
            }
        }
    }

    // epilogue
#pragma unroll
    for (int nt = 0; nt < 4; nt++) {
        int col = col0 + n_base + nt * 8 + 2 * tg;
        float2 bb2 = *(const float2*)(bias + col);
#pragma unroll
        for (int mt = 0; mt < 4; mt++) {
            int row = row0 + m_base + mt * 16 + grp;
            float v00 = actf<ACT>(acc[mt][nt][0] + bb2.x);
            float v01 = actf<ACT>(acc[mt][nt][1] + bb2.y);
            float v10 = actf<ACT>(acc[mt][nt][2] + bb2.x);
            float v11 = actf<ACT>(acc[mt][nt][3] + bb2.y);
            if (WOUT != 1) {
                __half2 h0 = __floats2half2_rn(v00, v01);
                __half2 h1 = __floats2half2_rn(v10, v11);
                *(__half2*)(Ch + (size_t)row * N + col) = h0;
                *(__half2*)(Ch + (size_t)(row + 8) * N + col) = h1;
            }
            if (WOUT != 0) {
                float2 f0 = {v00, v01}, f1 = {v10, v11};
                *(float2*)(Cf + (size_t)row * N + col) = f0;
                *(float2*)(Cf + (size_t)(row + 8) * N + col) = f1;
            }
        }
    }
}

// ---------- glue kernels ----------
__global__ void __launch_bounds__(256)
att_k(const __half* __restrict__ core, const float* __restrict__ W_att,
      const float* __restrict__ b_att, float* __restrict__ att)
{
    int w = (blockIdx.x * blockDim.x + threadIdx.x) >> 5;
    int l = threadIdx.x & 31;
    if (w >= NPAIR) return;
    const __half* r = core + (size_t)w * HCORE;
    float s = 0.0f;
#pragma unroll
    for (int k = l; k < HCORE; k += 32) s += __half2float(r[k]) * W_att[k];
#pragma unroll
    for (int o = 16; o; o >>= 1) s += __shfl_xor_sync(0xFFFFFFFFu, s, o);
    if (l == 0) att[w] = 1.0f / (1.0f + expf(-(s + b_att[0])));
}

__global__ void __launch_bounds__(256)
esum_k(const __half* __restrict__ ctx, const float* __restrict__ att,
       __half* __restrict__ E)
{
    int e = blockIdx.x;
    int c = threadIdx.x;
    float s = 0.0f;
#pragma unroll
    for (int jj = 0; jj < 7; jj++) {
        int p = e * 7 + jj;
        s += att[p] * __half2float(ctx[(size_t)p * HCTX + c]);
    }
    E[(size_t)e * HCTX + c] = __float2half(s);
}

__global__ void __launch_bounds__(256)
pack_k(const __half* __restrict__ S1, const __half* __restrict__ E,
       const __half* __restrict__ X, __half* __restrict__ T)
{
    int e = blockIdx.x;
    int t = threadIdx.x;
    T[(size_t)e * HTOT + t]       = S1[(size_t)e * HENC + t];
    T[(size_t)e * HTOT + 256 + t] = E[(size_t)e * HCTX + t];
    T[(size_t)e * HTOT + 512 + t] = X[(size_t)e * HIN + t];
    T[(size_t)e * HTOT + 768 + t] = X[(size_t)e * HIN + 256 + t];
}

#define SMEM128 (STAGES * (128 * ASTR + BBUF))   // 75776
#define SMEM256 (STAGES * (256 * ASTR + BBUF))   // 116736

extern "C" void kernel_launch(void* const* d_in, const int* in_sizes, int n_in,
                              void* d_out, int out_size)
{
    const float* inputs = (const float*)d_in[0];
    const float* state  = (const float*)d_in[1];
    const float* W_in   = (const float*)d_in[2];
    const float* b_in   = (const float*)d_in[3];
    const float* W_enc  = (const float*)d_in[4];
    const float* b_enc  = (const float*)d_in[5];
    const float* W_core = (const float*)d_in[6];
    const float* b_core = (const float*)d_in[7];
    const float* W_ctx  = (const float*)d_in[8];
    const float* b_ctx  = (const float*)d_in[9];
    const float* W_att  = (const float*)d_in[10];
    const float* b_att  = (const float*)d_in[11];
    const float* W_rec  = (const float*)d_in[12];
    const float* b_rec  = (const float*)d_in[13];
    const float* W_out  = (const float*)d_in[14];
    const float* b_out  = (const float*)d_in[15];

    float* out       = (float*)d_out;
    float* new_state = (float*)d_out + (size_t)BENT * MDIM;

    __half *pInh, *pSth, *pWinh, *pWench, *pWcoreh, *pWctxh, *pWrech, *pWouth;
    __half *pXh, *pS1h, *pCoreh, *pCtxh, *pEh, *pTh, *pNSh;
    float  *pAtt;
    cudaGetSymbolAddress((void**)&pInh,    g_inh);
    cudaGetSymbolAddress((void**)&pSth,    g_sth);
    cudaGetSymbolAddress((void**)&pWinh,   g_Winh);
    cudaGetSymbolAddress((void**)&pWench,  g_Wench);
    cudaGetSymbolAddress((void**)&pWcoreh, g_Wcoreh);
    cudaGetSymbolAddress((void**)&pWctxh,  g_Wctxh);
    cudaGetSymbolAddress((void**)&pWrech,  g_Wrech);
    cudaGetSymbolAddress((void**)&pWouth,  g_Wouth);
    cudaGetSymbolAddress((void**)&pXh,     g_Xh);
    cudaGetSymbolAddress((void**)&pS1h,    g_S1h);
    cudaGetSymbolAddress((void**)&pCoreh,  g_coreh);
    cudaGetSymbolAddress((void**)&pCtxh,   g_ctxh);
    cudaGetSymbolAddress((void**)&pAtt,    g_att);
    cudaGetSymbolAddress((void**)&pEh,     g_Eh);
    cudaGetSymbolAddress((void**)&pTh,     g_Th);
    cudaGetSymbolAddress((void**)&pNSh,    g_NSh);

    cudaFuncSetAttribute(hgemm<3,0,0,128>, cudaFuncAttributeMaxDynamicSharedMemorySize, SMEM128);
    cudaFuncSetAttribute(hgemm<1,0,0,128>, cudaFuncAttributeMaxDynamicSharedMemorySize, SMEM128);
    cudaFuncSetAttribute(hgemm<2,0,2,128>, cudaFuncAttributeMaxDynamicSharedMemorySize, SMEM128);
    cudaFuncSetAttribute(hgemm<1,1,0,256>, cudaFuncAttributeMaxDynamicSharedMemorySize, SMEM256);
    cudaFuncSetAttribute(hgemm<1,0,0,256>, cudaFuncAttributeMaxDynamicSharedMemorySize, SMEM256);
    cudaFuncSetAttribute(hgemm<2,0,1,256>, cudaFuncAttributeMaxDynamicSharedMemorySize, SMEM256);

    // 0) fp32 -> fp16 conversions
    cvt_k<<<(BENT*MDIM/8 + 255)/256, 256>>>(inputs, pInh, BENT*MDIM);
    cvt_k<<<(BENT*HSTATE/8 + 255)/256, 256>>>(state, pSth, BENT*HSTATE);
    cvt_k<<<(MDIM*HIN/8 + 255)/256, 256>>>(W_in, pWinh, MDIM*HIN);
    cvt_k<<<(HSTATE*HENC/8 + 255)/256, 256>>>(W_enc, pWench, HSTATE*HENC);
    cvt_k<<<(2*HENC*HCORE/8 + 255)/256, 256>>>(W_core, pWcoreh, 2*HENC*HCORE);
    cvt_k<<<(HCORE*HCTX/8 + 255)/256, 256>>>(W_ctx, pWctxh, HCORE*HCTX);
    cvt_k<<<(HTOT*HSTATE/8 + 255)/256, 256>>>(W_rec, pWrech, HTOT*HSTATE);
    cvt_k<<<(HSTATE*MDIM/8 + 255)/256, 256>>>(W_out, pWouth, HSTATE*MDIM);

    // 1) X = elu(inputs @ W_in)            [4096,512]  K=4096, BM=128
    hgemm<3,0,0,128><<<dim3(HIN/128, BENT/128), 256, SMEM128>>>(pInh, pWinh, b_in, pXh, nullptr, HIN, MDIM);
    // 2) S1 = relu(state @ W_enc)          [4096,256]  K=512, BM=128
    hgemm<1,0,0,128><<<dim3(HENC/128, BENT/128), 256, SMEM128>>>(pSth, pWench, b_enc, pS1h, nullptr, HENC, HSTATE);
    // 3) core = relu([cs|fs] @ W_core)     [28672,512] K=512 gathered, BM=256
    hgemm<1,1,0,256><<<dim3(HCORE/128, NPAIR/256), 512, SMEM256>>>(pS1h, pWcoreh, b_core, pCoreh, nullptr, HCORE, 2*HENC);
    // 4) ctx = relu(core @ W_ctx)          [28672,256] K=512, BM=256
    hgemm<1,0,0,256><<<dim3(HCTX/128, NPAIR/256), 512, SMEM256>>>(pCoreh, pWctxh, b_ctx, pCtxh, nullptr, HCTX, HCORE);
    // 5) att = sigmoid(core @ W_att)       [28672]
    att_k<<<(NPAIR * 32 + 255) / 256, 256>>>(pCoreh, W_att, b_att, pAtt);
    // 6) E = sum_j att*ctx                 [4096,256]
    esum_k<<<BENT, 256>>>(pCtxh, pAtt, pEh);
    // 7) T = [S1 | E | X]                  [4096,1024]
    pack_k<<<BENT, 256>>>(pS1h, pEh, pXh, pTh);
    // 8) new_state = sigmoid(T @ W_rec)    [4096,512]  K=1024, BM=128, fp32+fp16
    hgemm<2,0,2,128><<<dim3(HSTATE/128, BENT/128), 256, SMEM128>>>(pTh, pWrech, b_rec, pNSh, new_state, HSTATE, HTOT);
    // 9) out = sigmoid(new_state @ W_out)  [4096,4096] K=512, BM=256, fp32
    hgemm<2,0,1,256><<<dim3(MDIM/128, BENT/256), 512, SMEM256>>>(pNSh, pWouth, b_out, nullptr, out, MDIM, HSTATE);
}

// round 8
// speedup vs baseline: 1.3917x; 1.3917x over previous
#include <cuda_runtime.h>
#include <cuda_fp16.h>
#include <math.h>
#include <stdint.h>

// Problem dims (fixed)
#define KENT    8
#define BENT    4096
#define MDIM    4096
#define HIN     512
#define HENC    256
#define HCORE   512
#define HCTX    256
#define HSTATE  512
#define NPAIR   (BENT * (KENT - 1))   // 28672
#define HTOT    (HENC + HCTX + HIN)   // 1024

// ---- fp16 scratch (no allocation allowed) ----
__device__ __half g_inh[(size_t)BENT * MDIM];
__device__ __half g_sth[BENT * HSTATE];
__device__ __half g_Winh[MDIM * HIN];
__device__ __half g_Wench[HSTATE * HENC];
__device__ __half g_Wcoreh[2 * HENC * HCORE];
__device__ __half g_Wctxh[HCORE * HCTX];
__device__ __half g_Wrech[HTOT * HSTATE];
__device__ __half g_Wouth[HSTATE * MDIM];
__device__ __half g_Xh[BENT * HIN];
__device__ __half g_S1h[BENT * HENC];
__device__ __half g_coreh[(size_t)NPAIR * HCORE];
__device__ __half g_ctxh[(size_t)NPAIR * HCTX];
__device__ float  g_att[NPAIR];
__device__ __half g_Eh[BENT * HCTX];
__device__ __half g_Th[BENT * HTOT];
__device__ __half g_NSh[BENT * HSTATE];

template<int ACT>
__device__ __forceinline__ float actf(float v) {
    if (ACT == 1) return fmaxf(v, 0.0f);                  // relu
    if (ACT == 2) return 1.0f / (1.0f + expf(-v));        // sigmoid
    if (ACT == 3) return v > 0.0f ? v : expm1f(v);        // elu
    return v;
}

// fp32 -> fp16 bulk convert, 8 elems/thread
__global__ void __launch_bounds__(256)
cvt_k(const float* __restrict__ s, __half* __restrict__ d, int n)
{
    int i = (blockIdx.x * blockDim.x + threadIdx.x) * 8;
    if (i >= n) return;
    float4 a = *(const float4*)(s + i);
    float4 b = *(const float4*)(s + i + 4);
    __half2 h0 = __floats2half2_rn(a.x, a.y);
    __half2 h1 = __floats2half2_rn(a.z, a.w);
    __half2 h2 = __floats2half2_rn(b.x, b.y);
    __half2 h3 = __floats2half2_rn(b.z, b.w);
    uint4 o;
    o.x = *(uint32_t*)&h0; o.y = *(uint32_t*)&h1;
    o.z = *(uint32_t*)&h2; o.w = *(uint32_t*)&h3;
    *(uint4*)(d + i) = o;
}

#define STAGES 4
#define ASTR 80                       // A row: 32 fp16 + 16B pad
#define BSTR 272                      // B row: 128 fp16 + 16B pad
#define BBUF (32 * BSTR)              // 8704

__device__ __forceinline__ void cp16(uint32_t dst, const void* src) {
    asm volatile("cp.async.cg.shared.global [%0], [%1], 16;" :: "r"(dst), "l"(src));
}

// fp16 tensor-core GEMM, cp.async 4-stage pipeline. 256 threads, 8 warps (2x4).
// CTA tile BM x 128. BM=128: warp tile 64x32 (R5 proven). BM=64: warp tile 32x32
// (higher occupancy, 3 CTAs/SM, for narrow-grid GEMMs).
// MODE 0: normal A. MODE 1: pair-gathered A from S1h (K = 2*HENC).
// WOUT 0: fp16 C. 1: fp32 C. 2: both.
template<int ACT, int MODE, int WOUT, int BM>
__global__ void __launch_bounds__(256, (BM == 64) ? 3 : 1)
hgemm(const __half* __restrict__ A, const __half* __restrict__ B,
      const float* __restrict__ bias, __half* __restrict__ Ch,
      float* __restrict__ Cf, int N, int K)
{
    constexpr int MT   = BM / 32;             // m16 tiles per warp (4 or 2)
    constexpr int ABUF = BM * ASTR;
    constexpr int STGB = ABUF + BBUF;

    extern __shared__ char sm[];
    const uint32_t smb = (uint32_t)__cvta_generic_to_shared(sm);

    const int tid  = threadIdx.x;
    const int warp = tid >> 5;
    const int lane = tid & 31;
    const int row0 = blockIdx.y * BM;
    const int col0 = blockIdx.x * 128;

    const int wm = warp >> 2, wn = warp & 3;
    const int m_base = wm * (BM / 2), n_base = wn * 32;
    const int grp = lane >> 2, tg = lane & 3;

    // ldmatrix lane offsets (proven layout)
    const int a_row = (lane & 7) + ((lane >> 3) & 1) * 8;
    const int a_kh  = (lane >> 4) * 8;
    const uint32_t aLane = (uint32_t)((m_base + a_row) * ASTR + a_kh * 2);
    const int b_k  = (lane & 7) + ((lane >> 3) & 1) * 8;
    const int b_nh = (lane >> 4) * 8;
    const uint32_t bLane = (uint32_t)(b_k * BSTR + (n_base + b_nh) * 2);

    // ---- cp.async loader assignments ----
    // A: BM rows x 64B. BM=128: 2 thr/row x 2 cp16. BM=64: 4 thr/row x 1 cp16.
    const int arow = (BM == 128) ? (tid >> 1) : (tid >> 2);
    const int ak16 = (BM == 128) ? ((tid & 1) * 16) : ((tid & 3) * 8);
    const uint32_t aoff = (uint32_t)(arow * ASTR + ak16 * 2);
    size_t rcs = 0, rfs = 0;
    const __half* aBase = nullptr;
    if (MODE == 0) {
        aBase = A + (size_t)(row0 + arow) * K + ak16;
    } else {
        int p = row0 + arow;
        int b_ = p / 56, rem = p % 56;
        int ii = rem / 7, jj = rem % 7;
        int j = jj + (jj >= ii ? 1 : 0);
        rcs = (size_t)(b_ * KENT + j) * HENC;
        rfs = (size_t)(b_ * KENT + ii) * HENC;
    }
    // B: 32 rows x 256B; 8 thr/row x 2 cp16 (256 threads).
    const int brow = tid >> 3;
    const int bo16 = (tid & 7) * 16;
    const uint32_t boff = (uint32_t)(brow * BSTR + bo16 * 2);
    const __half* bBase = B + (size_t)brow * N + col0 + bo16;

    auto issue_stage = [&](int s, int kg) {
        uint32_t ab = smb + (uint32_t)s * STGB;
        uint32_t bb = ab + ABUF;
        const __half* asrc;
        if (MODE == 0) {
            asrc = aBase + kg;
        } else {
            int kk = kg + ak16;
            asrc = (kk < HENC) ? (A + rcs + kk) : (A + rfs + (kk - HENC));
        }
        cp16(ab + aoff, asrc);
        if (BM == 128) cp16(ab + aoff + 16, asrc + 8);
        const __half* bsrc = bBase + (size_t)kg * N;
        cp16(bb + boff, bsrc);
        cp16(bb + boff + 16, bsrc + 8);
    };

    float acc[MT][4][4];
#pragma unroll
    for (int mt = 0; mt < MT; mt++)
#pragma unroll
        for (int nt = 0; nt < 4; nt++)
#pragma unroll
            for (int c = 0; c < 4; c++) acc[mt][nt][c] = 0.0f;

    const int nk = K >> 5;

#pragma unroll
    for (int s = 0; s < STAGES - 1; s++) {
        if (s < nk) issue_stage(s, s << 5);
        asm volatile("cp.async.commit_group;" ::: "memory");
    }

    for (int it = 0; it < nk; ++it) {
        asm volatile("cp.async.wait_group %0;" :: "n"(STAGES - 2) : "memory");
        __syncthreads();
        const int nxt = it + STAGES - 1;
        if (nxt < nk) issue_stage(nxt & (STAGES - 1), nxt << 5);
        asm volatile("cp.async.commit_group;" ::: "memory");

        const uint32_t ab = smb + (uint32_t)(it & (STAGES - 1)) * STGB + aLane;
        const uint32_t bb = smb + (uint32_t)(it & (STAGES - 1)) * STGB + ABUF + bLane;
#pragma unroll
        for (int ks = 0; ks < 2; ks++) {
            uint32_t af[MT][4];
#pragma unroll
            for (int mt = 0; mt < MT; mt++) {
                uint32_t addr = ab + mt * (16 * ASTR) + ks * 32;
                asm volatile("ldmatrix.sync.aligned.m8n8.x4.shared.b16 {%0,%1,%2,%3}, [%4];"
                             : "=r"(af[mt][0]), "=r"(af[mt][1]),
                               "=r"(af[mt][2]), "=r"(af[mt][3])
                             : "r"(addr));
            }
            uint32_t bf[4][2];
#pragma unroll
            for (int nl = 0; nl < 2; nl++) {
                uint32_t addr = bb + nl * 32 + ks * (16 * BSTR);
                asm volatile("ldmatrix.sync.aligned.m8n8.x4.trans.shared.b16 {%0,%1,%2,%3}, [%4];"
                             : "=r"(bf[nl*2][0]), "=r"(bf[nl*2][1]),
                               "=r"(bf[nl*2+1][0]), "=r"(bf[nl*2+1][1])
                             : "r"(addr));
            }
#pragma unroll
            for (int mt = 0; mt < MT; mt++) {
#pragma unroll
                for (int nt = 0; nt < 4; nt++) {
                    asm("mma.sync.aligned.m16n8k16.row.col.f32.f16.f16.f32 "
                        "{%0,%1,%2,%3}, {%4,%5,%6,%7}, {%8,%9}, {%0,%1,%2,%3};"
                        : "+f"(acc[mt][nt][0]), "+f"(acc[mt][nt][1]),
                          "+f"(acc[mt][nt][2]), "+f"(acc[mt][nt][3])
                        : "r"(af[mt][0]), "r"(af[mt][1]), "r"(af[mt][2]), "r"(af[mt][3]),
                          "r"(bf[nt][0]), "r"(bf[nt][1]));
                }
            }
        }
    }

    // epilogue
#pragma unroll
    for (int nt = 0; nt < 4; nt++) {
        int col = col0 + n_base + nt * 8 + 2 * tg;
        float2 bb2 = *(const float2*)(bias + col);
#pragma unroll
        for (int mt = 0; mt < MT; mt++) {
            int row = row0 + m_base + mt * 16 + grp;
            float v00 = actf<ACT>(acc[mt][nt][0] + bb2.x);
            float v01 = actf<ACT>(acc[mt][nt][1] + bb2.y);
            float v10 = actf<ACT>(acc[mt][nt][2] + bb2.x);
            float v11 = actf<ACT>(acc[mt][nt][3] + bb2.y);
            if (WOUT != 1) {
                __half2 h0 = __floats2half2_rn(v00, v01);
                __half2 h1 = __floats2half2_rn(v10, v11);
                *(__half2*)(Ch + (size_t)row * N + col) = h0;
                *(__half2*)(Ch + (size_t)(row + 8) * N + col) = h1;
            }
            if (WOUT != 0) {
                float2 f0 = {v00, v01}, f1 = {v10, v11};
                *(float2*)(Cf + (size_t)row * N + col) = f0;
                *(float2*)(Cf + (size_t)(row + 8) * N + col) = f1;
            }
        }
    }
}

// ---------- glue kernels ----------
__global__ void __launch_bounds__(256)
att_k(const __half* __restrict__ core, const float* __restrict__ W_att,
      const float* __restrict__ b_att, float* __restrict__ att)
{
    int w = (blockIdx.x * blockDim.x + threadIdx.x) >> 5;
    int l = threadIdx.x & 31;
    if (w >= NPAIR) return;
    const __half* r = core + (size_t)w * HCORE;
    float s = 0.0f;
#pragma unroll
    for (int k = l; k < HCORE; k += 32) s += __half2float(r[k]) * W_att[k];
#pragma unroll
    for (int o = 16; o; o >>= 1) s += __shfl_xor_sync(0xFFFFFFFFu, s, o);
    if (l == 0) att[w] = 1.0f / (1.0f + expf(-(s + b_att[0])));
}

__global__ void __launch_bounds__(256)
esum_k(const __half* __restrict__ ctx, const float* __restrict__ att,
       __half* __restrict__ E)
{
    int e = blockIdx.x;
    int c = threadIdx.x;
    float s = 0.0f;
#pragma unroll
    for (int jj = 0; jj < 7; jj++) {
        int p = e * 7 + jj;
        s += att[p] * __half2float(ctx[(size_t)p * HCTX + c]);
    }
    E[(size_t)e * HCTX + c] = __float2half(s);
}

__global__ void __launch_bounds__(256)
pack_k(const __half* __restrict__ S1, const __half* __restrict__ E,
       const __half* __restrict__ X, __half* __restrict__ T)
{
    int e = blockIdx.x;
    int t = threadIdx.x;
    T[(size_t)e * HTOT + t]       = S1[(size_t)e * HENC + t];
    T[(size_t)e * HTOT + 256 + t] = E[(size_t)e * HCTX + t];
    T[(size_t)e * HTOT + 512 + t] = X[(size_t)e * HIN + t];
    T[(size_t)e * HTOT + 768 + t] = X[(size_t)e * HIN + 256 + t];
}

#define SMEM128 (STAGES * (128 * ASTR + BBUF))   // 75776
#define SMEM64  (STAGES * (64 * ASTR + BBUF))    // 55296

extern "C" void kernel_launch(void* const* d_in, const int* in_sizes, int n_in,
                              void* d_out, int out_size)
{
    const float* inputs = (const float*)d_in[0];
    const float* state  = (const float*)d_in[1];
    const float* W_in   = (const float*)d_in[2];
    const float* b_in   = (const float*)d_in[3];
    const float* W_enc  = (const float*)d_in[4];
    const float* b_enc  = (const float*)d_in[5];
    const float* W_core = (const float*)d_in[6];
    const float* b_core = (const float*)d_in[7];
    const float* W_ctx  = (const float*)d_in[8];
    const float* b_ctx  = (const float*)d_in[9];
    const float* W_att  = (const float*)d_in[10];
    const float* b_att  = (const float*)d_in[11];
    const float* W_rec  = (const float*)d_in[12];
    const float* b_rec  = (const float*)d_in[13];
    const float* W_out  = (const float*)d_in[14];
    const float* b_out  = (const float*)d_in[15];

    float* out       = (float*)d_out;
    float* new_state = (float*)d_out + (size_t)BENT * MDIM;

    __half *pInh, *pSth, *pWinh, *pWench, *pWcoreh, *pWctxh, *pWrech, *pWouth;
    __half *pXh, *pS1h, *pCoreh, *pCtxh, *pEh, *pTh, *pNSh;
    float  *pAtt;
    cudaGetSymbolAddress((void**)&pInh,    g_inh);
    cudaGetSymbolAddress((void**)&pSth,    g_sth);
    cudaGetSymbolAddress((void**)&pWinh,   g_Winh);
    cudaGetSymbolAddress((void**)&pWench,  g_Wench);
    cudaGetSymbolAddress((void**)&pWcoreh, g_Wcoreh);
    cudaGetSymbolAddress((void**)&pWctxh,  g_Wctxh);
    cudaGetSymbolAddress((void**)&pWrech,  g_Wrech);
    cudaGetSymbolAddress((void**)&pWouth,  g_Wouth);
    cudaGetSymbolAddress((void**)&pXh,     g_Xh);
    cudaGetSymbolAddress((void**)&pS1h,    g_S1h);
    cudaGetSymbolAddress((void**)&pCoreh,  g_coreh);
    cudaGetSymbolAddress((void**)&pCtxh,   g_ctxh);
    cudaGetSymbolAddress((void**)&pAtt,    g_att);
    cudaGetSymbolAddress((void**)&pEh,     g_Eh);
    cudaGetSymbolAddress((void**)&pTh,     g_Th);
    cudaGetSymbolAddress((void**)&pNSh,    g_NSh);

    cudaFuncSetAttribute(hgemm<3,0,0,64>,  cudaFuncAttributeMaxDynamicSharedMemorySize, SMEM64);
    cudaFuncSetAttribute(hgemm<1,0,0,64>,  cudaFuncAttributeMaxDynamicSharedMemorySize, SMEM64);
    cudaFuncSetAttribute(hgemm<2,0,2,64>,  cudaFuncAttributeMaxDynamicSharedMemorySize, SMEM64);
    cudaFuncSetAttribute(hgemm<1,1,0,128>, cudaFuncAttributeMaxDynamicSharedMemorySize, SMEM128);
    cudaFuncSetAttribute(hgemm<1,0,0,128>, cudaFuncAttributeMaxDynamicSharedMemorySize, SMEM128);
    cudaFuncSetAttribute(hgemm<2,0,1,128>, cudaFuncAttributeMaxDynamicSharedMemorySize, SMEM128);

    // 0) fp32 -> fp16 conversions
    cvt_k<<<(BENT*MDIM/8 + 255)/256, 256>>>(inputs, pInh, BENT*MDIM);
    cvt_k<<<(BENT*HSTATE/8 + 255)/256, 256>>>(state, pSth, BENT*HSTATE);
    cvt_k<<<(MDIM*HIN/8 + 255)/256, 256>>>(W_in, pWinh, MDIM*HIN);
    cvt_k<<<(HSTATE*HENC/8 + 255)/256, 256>>>(W_enc, pWench, HSTATE*HENC);
    cvt_k<<<(2*HENC*HCORE/8 + 255)/256, 256>>>(W_core, pWcoreh, 2*HENC*HCORE);
    cvt_k<<<(HCORE*HCTX/8 + 255)/256, 256>>>(W_ctx, pWctxh, HCORE*HCTX);
    cvt_k<<<(HTOT*HSTATE/8 + 255)/256, 256>>>(W_rec, pWrech, HTOT*HSTATE);
    cvt_k<<<(HSTATE*MDIM/8 + 255)/256, 256>>>(W_out, pWouth, HSTATE*MDIM);

    // 1) X = elu(inputs @ W_in)            [4096,512]  K=4096, BM=64 (256 CTAs)
    hgemm<3,0,0,64><<<dim3(HIN/128, BENT/64), 256, SMEM64>>>(pInh, pWinh, b_in, pXh, nullptr, HIN, MDIM);
    // 2) S1 = relu(state @ W_enc)          [4096,256]  K=512, BM=64 (128 CTAs)
    hgemm<1,0,0,64><<<dim3(HENC/128, BENT/64), 256, SMEM64>>>(pSth, pWench, b_enc, pS1h, nullptr, HENC, HSTATE);
    // 3) core = relu([cs|fs] @ W_core)     [28672,512] K=512 gathered, BM=128
    hgemm<1,1,0,128><<<dim3(HCORE/128, NPAIR/128), 256, SMEM128>>>(pS1h, pWcoreh, b_core, pCoreh, nullptr, HCORE, 2*HENC);
    // 4) ctx = relu(core @ W_ctx)          [28672,256] K=512, BM=128
    hgemm<1,0,0,128><<<dim3(HCTX/128, NPAIR/128), 256, SMEM128>>>(pCoreh, pWctxh, b_ctx, pCtxh, nullptr, HCTX, HCORE);
    // 5) att = sigmoid(core @ W_att)       [28672]
    att_k<<<(NPAIR * 32 + 255) / 256, 256>>>(pCoreh, W_att, b_att, pAtt);
    // 6) E = sum_j att*ctx                 [4096,256]
    esum_k<<<BENT, 256>>>(pCtxh, pAtt, pEh);
    // 7) T = [S1 | E | X]                  [4096,1024]
    pack_k<<<BENT, 256>>>(pS1h, pEh, pXh, pTh);
    // 8) new_state = sigmoid(T @ W_rec)    [4096,512]  K=1024, BM=64 (256 CTAs)
    hgemm<2,0,2,64><<<dim3(HSTATE/128, BENT/64), 256, SMEM64>>>(pTh, pWrech, b_rec, pNSh, new_state, HSTATE, HTOT);
    // 9) out = sigmoid(new_state @ W_out)  [4096,4096] K=512, BM=128
    hgemm<2,0,1,128><<<dim3(MDIM/128, BENT/128), 256, SMEM128>>>(pNSh, pWouth, b_out, nullptr, out, MDIM, HSTATE);
}

// round 9
// speedup vs baseline: 1.5124x; 1.0867x over previous
#include <cuda_runtime.h>
#include <cuda_fp16.h>
#include <math.h>
#include <stdint.h>

// Problem dims (fixed)
#define KENT    8
#define BENT    4096
#define MDIM    4096
#define HIN     512
#define HENC    256
#define HCORE   512
#define HCTX    256
#define HSTATE  512
#define NPAIR   (BENT * (KENT - 1))   // 28672
#define HTOT    (HENC + HCTX + HIN)   // 1024

// ---- fp16 scratch (no allocation allowed) ----
__device__ __half g_inh[(size_t)BENT * MDIM];
__device__ __half g_sth[BENT * HSTATE];
__device__ __half g_Winh[MDIM * HIN];
__device__ __half g_Wench[HSTATE * HENC];
__device__ __half g_Wcoreh[2 * HENC * HCORE];
__device__ __half g_Wctxh[HCORE * HCTX];
__device__ __half g_Wrech[HTOT * HSTATE];
__device__ __half g_Wouth[HSTATE * MDIM];
__device__ __half g_Xh[BENT * HIN];
__device__ __half g_S1h[BENT * HENC];
__device__ __half g_coreh[(size_t)NPAIR * HCORE];
__device__ __half g_ctxh[(size_t)NPAIR * HCTX];
__device__ float  g_att[NPAIR];
__device__ __half g_Th[BENT * HTOT];
__device__ __half g_NSh[BENT * HSTATE];
__device__ float  g_part[2 * (size_t)BENT * HIN];   // split-K partials (16 MB)

template<int ACT>
__device__ __forceinline__ float actf(float v) {
    if (ACT == 1) return fmaxf(v, 0.0f);                  // relu
    if (ACT == 2) return 1.0f / (1.0f + expf(-v));        // sigmoid
    if (ACT == 3) return v > 0.0f ? v : expm1f(v);        // elu
    return v;
}

// ---- fused fp32->fp16 conversion over 8 fixed segments ----
struct CvtArgs { const float* s[8]; __half* d[8]; };
__constant__ long long c_dummy; // keep struct pass-by-value simple

__global__ void __launch_bounds__(256)
cvtall_k(CvtArgs a)
{
    long long i = ((long long)blockIdx.x * 256 + threadIdx.x) * 8;
    int seg; long long off;
    if      (i < 16777216LL) { seg = 0; off = i; }
    else if (i < 18874368LL) { seg = 1; off = i - 16777216LL; }
    else if (i < 20971520LL) { seg = 2; off = i - 18874368LL; }
    else if (i < 21102592LL) { seg = 3; off = i - 20971520LL; }
    else if (i < 21364736LL) { seg = 4; off = i - 21102592LL; }
    else if (i < 21495808LL) { seg = 5; off = i - 21364736LL; }
    else if (i < 22020096LL) { seg = 6; off = i - 21495808LL; }
    else if (i < 24117248LL) { seg = 7; off = i - 22020096LL; }
    else return;
    const float* s = a.s[seg] + off;
    __half* d = a.d[seg] + off;
    float4 x = *(const float4*)s;
    float4 y = *(const float4*)(s + 4);
    __half2 h0 = __floats2half2_rn(x.x, x.y);
    __half2 h1 = __floats2half2_rn(x.z, x.w);
    __half2 h2 = __floats2half2_rn(y.x, y.y);
    __half2 h3 = __floats2half2_rn(y.z, y.w);
    uint4 o;
    o.x = *(uint32_t*)&h0; o.y = *(uint32_t*)&h1;
    o.z = *(uint32_t*)&h2; o.w = *(uint32_t*)&h3;
    *(uint4*)d = o;
}

#define STAGES 4
#define ASTR 80                       // A row: 32 fp16 + 16B pad
#define BSTR 272                      // B row: 128 fp16 + 16B pad
#define BBUF (32 * BSTR)              // 8704
#define ABUF (128 * ASTR)             // 10240
#define STGB (ABUF + BBUF)
#define SMEM128 (STAGES * STGB)       // 75776

__device__ __forceinline__ void cp16(uint32_t dst, const void* src) {
    asm volatile("cp.async.cg.shared.global [%0], [%1], 16;" :: "r"(dst), "l"(src));
}

// fp16 tensor-core GEMM, cp.async 4-stage pipeline (R5-proven shape).
// 128x128 CTA tile, BK=32, 256 threads, 8 warps 2x4, warp tile 64x32.
// MODE 0: normal A. MODE 1: pair-gathered A from S1h (K = 2*HENC).
// WOUT 0: fp16 C. 1: fp32 C. 2: both.
// SPLIT 1: gridDim.z=2 split-K, raw fp32 partials to Cf + z*M*N (no bias/act).
template<int ACT, int MODE, int WOUT, int SPLIT>
__global__ void __launch_bounds__(256)
hgemm(const __half* __restrict__ A, const __half* __restrict__ B,
      const float* __restrict__ bias, __half* __restrict__ Ch,
      float* __restrict__ Cf, int N, int K)
{
    extern __shared__ char sm[];
    const uint32_t smb = (uint32_t)__cvta_generic_to_shared(sm);

    const int tid  = threadIdx.x;
    const int warp = tid >> 5;
    const int lane = tid & 31;
    const int row0 = blockIdx.y * 128;
    const int col0 = blockIdx.x * 128;
    const int z    = SPLIT ? blockIdx.z : 0;
    const int KR   = SPLIT ? (K >> 1) : K;     // reduced-K per z
    const int kbeg = z * KR;

    const int wm = warp >> 2, wn = warp & 3;
    const int m_base = wm * 64, n_base = wn * 32;
    const int grp = lane >> 2, tg = lane & 3;

    // ldmatrix lane offsets (proven layout)
    const int a_row = (lane & 7) + ((lane >> 3) & 1) * 8;
    const int a_kh  = (lane >> 4) * 8;
    const uint32_t aLane = (uint32_t)((m_base + a_row) * ASTR + a_kh * 2);
    const int b_k  = (lane & 7) + ((lane >> 3) & 1) * 8;
    const int b_nh = (lane >> 4) * 8;
    const uint32_t bLane = (uint32_t)(b_k * BSTR + (n_base + b_nh) * 2);

    // ---- cp.async loader assignments ----
    const int arow = tid >> 1;
    const int ak16 = (tid & 1) * 16;
    const uint32_t aoff = (uint32_t)(arow * ASTR + ak16 * 2);
    size_t rcs = 0, rfs = 0;
    const __half* aBase = nullptr;
    if (MODE == 0) {
        aBase = A + (size_t)(row0 + arow) * K + ak16;
    } else {
        int p = row0 + arow;
        int b_ = p / 56, rem = p % 56;
        int ii = rem / 7, jj = rem % 7;
        int j = jj + (jj >= ii ? 1 : 0);
        rcs = (size_t)(b_ * KENT + j) * HENC;
        rfs = (size_t)(b_ * KENT + ii) * HENC;
    }
    const int brow = tid >> 3;
    const int bo16 = (tid & 7) * 16;
    const uint32_t boff = (uint32_t)(brow * BSTR + bo16 * 2);
    const __half* bBase = B + (size_t)brow * N + col0 + bo16;

    auto issue_stage = [&](int s, int kg) {   // kg is absolute k offset
        uint32_t ab = smb + (uint32_t)s * STGB;
        uint32_t bb = ab + ABUF;
        const __half* asrc;
        if (MODE == 0) {
            asrc = aBase + kg;
        } else {
            int kk = kg + ak16;
            asrc = (kk < HENC) ? (A + rcs + kk) : (A + rfs + (kk - HENC));
        }
        cp16(ab + aoff, asrc);
        cp16(ab + aoff + 16, asrc + 8);
        const __half* bsrc = bBase + (size_t)kg * N;
        cp16(bb + boff, bsrc);
        cp16(bb + boff + 16, bsrc + 8);
    };

    float acc[4][4][4];
#pragma unroll
    for (int mt = 0; mt < 4; mt++)
#pragma unroll
        for (int nt = 0; nt < 4; nt++)
#pragma unroll
            for (int c = 0; c < 4; c++) acc[mt][nt][c] = 0.0f;

    const int nk = KR >> 5;

#pragma unroll
    for (int s = 0; s < STAGES - 1; s++) {
        if (s < nk) issue_stage(s, kbeg + (s << 5));
        asm volatile("cp.async.commit_group;" ::: "memory");
    }

    for (int it = 0; it < nk; ++it) {
        asm volatile("cp.async.wait_group %0;" :: "n"(STAGES - 2) : "memory");
        __syncthreads();
        const int nxt = it + STAGES - 1;
        if (nxt < nk) issue_stage(nxt & (STAGES - 1), kbeg + (nxt << 5));
        asm volatile("cp.async.commit_group;" ::: "memory");

        const uint32_t ab = smb + (uint32_t)(it & (STAGES - 1)) * STGB + aLane;
        const uint32_t bb = smb + (uint32_t)(it & (STAGES - 1)) * STGB + ABUF + bLane;
#pragma unroll
        for (int ks = 0; ks < 2; ks++) {
            uint32_t af[4][4];
#pragma unroll
            for (int mt = 0; mt < 4; mt++) {
                uint32_t addr = ab + mt * (16 * ASTR) + ks * 32;
                asm volatile("ldmatrix.sync.aligned.m8n8.x4.shared.b16 {%0,%1,%2,%3}, [%4];"
                             : "=r"(af[mt][0]), "=r"(af[mt][1]),
                               "=r"(af[mt][2]), "=r"(af[mt][3])
                             : "r"(addr));
            }
            uint32_t bf[4][2];
#pragma unroll
            for (int nl = 0; nl < 2; nl++) {
                uint32_t addr = bb + nl * 32 + ks * (16 * BSTR);
                asm volatile("ldmatrix.sync.aligned.m8n8.x4.trans.shared.b16 {%0,%1,%2,%3}, [%4];"
                             : "=r"(bf[nl*2][0]), "=r"(bf[nl*2][1]),
                               "=r"(bf[nl*2+1][0]), "=r"(bf[nl*2+1][1])
                             : "r"(addr));
            }
#pragma unroll
            for (int mt = 0; mt < 4; mt++) {
#pragma unroll
                for (int nt = 0; nt < 4; nt++) {
                    asm("mma.sync.aligned.m16n8k16.row.col.f32.f16.f16.f32 "
                        "{%0,%1,%2,%3}, {%4,%5,%6,%7}, {%8,%9}, {%0,%1,%2,%3};"
                        : "+f"(acc[mt][nt][0]), "+f"(acc[mt][nt][1]),
                          "+f"(acc[mt][nt][2]), "+f"(acc[mt][nt][3])
                        : "r"(af[mt][0]), "r"(af[mt][1]), "r"(af[mt][2]), "r"(af[mt][3]),
                          "r"(bf[nt][0]), "r"(bf[nt][1]));
                }
            }
        }
    }

    // epilogue
    if (SPLIT) {
        float* Cz = Cf + (size_t)z * ((size_t)gridDim.y * 128) * N;
#pragma unroll
        for (int nt = 0; nt < 4; nt++) {
            int col = col0 + n_base + nt * 8 + 2 * tg;
#pragma unroll
            for (int mt = 0; mt < 4; mt++) {
                int row = row0 + m_base + mt * 16 + grp;
                float2 f0 = {acc[mt][nt][0], acc[mt][nt][1]};
                float2 f1 = {acc[mt][nt][2], acc[mt][nt][3]};
                *(float2*)(Cz + (size_t)row * N + col) = f0;
                *(float2*)(Cz + (size_t)(row + 8) * N + col) = f1;
            }
        }
        return;
    }
#pragma unroll
    for (int nt = 0; nt < 4; nt++) {
        int col = col0 + n_base + nt * 8 + 2 * tg;
        float2 bb2 = *(const float2*)(bias + col);
#pragma unroll
        for (int mt = 0; mt < 4; mt++) {
            int row = row0 + m_base + mt * 16 + grp;
            float v00 = actf<ACT>(acc[mt][nt][0] + bb2.x);
            float v01 = actf<ACT>(acc[mt][nt][1] + bb2.y);
            float v10 = actf<ACT>(acc[mt][nt][2] + bb2.x);
            float v11 = actf<ACT>(acc[mt][nt][3] + bb2.y);
            if (WOUT != 1) {
                __half2 h0 = __floats2half2_rn(v00, v01);
                __half2 h1 = __floats2half2_rn(v10, v11);
                *(__half2*)(Ch + (size_t)row * N + col) = h0;
                *(__half2*)(Ch + (size_t)(row + 8) * N + col) = h1;
            }
            if (WOUT != 0) {
                float2 f0 = {v00, v01}, f1 = {v10, v11};
                *(float2*)(Cf + (size_t)row * N + col) = f0;
                *(float2*)(Cf + (size_t)(row + 8) * N + col) = f1;
            }
        }
    }
}

// split-K combine for X: Xh = elu(p0 + p1 + bias), fp16 out
__global__ void __launch_bounds__(256)
xcomb_k(const float* __restrict__ p, const float* __restrict__ bias,
        __half* __restrict__ Xh)
{
    int i = (blockIdx.x * 256 + threadIdx.x) * 4;
    const size_t H = (size_t)BENT * HIN;
    float4 a = *(const float4*)(p + i);
    float4 b = *(const float4*)(p + H + i);
    float4 bb = *(const float4*)(bias + (i & (HIN - 1)));
    float v0 = a.x + b.x + bb.x;
    float v1 = a.y + b.y + bb.y;
    float v2 = a.z + b.z + bb.z;
    float v3 = a.w + b.w + bb.w;
    v0 = v0 > 0.f ? v0 : expm1f(v0);
    v1 = v1 > 0.f ? v1 : expm1f(v1);
    v2 = v2 > 0.f ? v2 : expm1f(v2);
    v3 = v3 > 0.f ? v3 : expm1f(v3);
    __half2 h0 = __floats2half2_rn(v0, v1);
    __half2 h1 = __floats2half2_rn(v2, v3);
    uint2 o;
    o.x = *(uint32_t*)&h0; o.y = *(uint32_t*)&h1;
    *(uint2*)(Xh + i) = o;
}

// ---------- glue kernels ----------
__global__ void __launch_bounds__(256)
att_k(const __half* __restrict__ core, const float* __restrict__ W_att,
      const float* __restrict__ b_att, float* __restrict__ att)
{
    int w = (blockIdx.x * blockDim.x + threadIdx.x) >> 5;
    int l = threadIdx.x & 31;
    if (w >= NPAIR) return;
    const __half* r = core + (size_t)w * HCORE;
    float s = 0.0f;
#pragma unroll
    for (int k = l; k < HCORE; k += 32) s += __half2float(r[k]) * W_att[k];
#pragma unroll
    for (int o = 16; o; o >>= 1) s += __shfl_xor_sync(0xFFFFFFFFu, s, o);
    if (l == 0) att[w] = 1.0f / (1.0f + expf(-(s + b_att[0])));
}

// fused: E = sum_j att*ctx, then T = [S1 | E | X]
__global__ void __launch_bounds__(256)
ep_k(const __half* __restrict__ ctx, const float* __restrict__ att,
     const __half* __restrict__ S1, const __half* __restrict__ X,
     __half* __restrict__ T)
{
    int e = blockIdx.x;
    int t = threadIdx.x;
    float s = 0.0f;
#pragma unroll
    for (int jj = 0; jj < 7; jj++) {
        int p = e * 7 + jj;
        s += att[p] * __half2float(ctx[(size_t)p * HCTX + t]);
    }
    T[(size_t)e * HTOT + 256 + t] = __float2half(s);
    T[(size_t)e * HTOT + t]       = S1[(size_t)e * HENC + t];
    T[(size_t)e * HTOT + 512 + t] = X[(size_t)e * HIN + t];
    T[(size_t)e * HTOT + 768 + t] = X[(size_t)e * HIN + 256 + t];
}

extern "C" void kernel_launch(void* const* d_in, const int* in_sizes, int n_in,
                              void* d_out, int out_size)
{
    const float* inputs = (const float*)d_in[0];
    const float* state  = (const float*)d_in[1];
    const float* W_in   = (const float*)d_in[2];
    const float* b_in   = (const float*)d_in[3];
    const float* W_enc  = (const float*)d_in[4];
    const float* b_enc  = (const float*)d_in[5];
    const float* W_core = (const float*)d_in[6];
    const float* b_core = (const float*)d_in[7];
    const float* W_ctx  = (const float*)d_in[8];
    const float* b_ctx  = (const float*)d_in[9];
    const float* W_att  = (const float*)d_in[10];
    const float* b_att  = (const float*)d_in[11];
    const float* W_rec  = (const float*)d_in[12];
    const float* b_rec  = (const float*)d_in[13];
    const float* W_out  = (const float*)d_in[14];
    const float* b_out  = (const float*)d_in[15];

    float* out       = (float*)d_out;
    float* new_state = (float*)d_out + (size_t)BENT * MDIM;

    __half *pInh, *pSth, *pWinh, *pWench, *pWcoreh, *pWctxh, *pWrech, *pWouth;
    __half *pXh, *pS1h, *pCoreh, *pCtxh, *pTh, *pNSh;
    float  *pAtt, *pPart;
    cudaGetSymbolAddress((void**)&pInh,    g_inh);
    cudaGetSymbolAddress((void**)&pSth,    g_sth);
    cudaGetSymbolAddress((void**)&pWinh,   g_Winh);
    cudaGetSymbolAddress((void**)&pWench,  g_Wench);
    cudaGetSymbolAddress((void**)&pWcoreh, g_Wcoreh);
    cudaGetSymbolAddress((void**)&pWctxh,  g_Wctxh);
    cudaGetSymbolAddress((void**)&pWrech,  g_Wrech);
    cudaGetSymbolAddress((void**)&pWouth,  g_Wouth);
    cudaGetSymbolAddress((void**)&pXh,     g_Xh);
    cudaGetSymbolAddress((void**)&pS1h,    g_S1h);
    cudaGetSymbolAddress((void**)&pCoreh,  g_coreh);
    cudaGetSymbolAddress((void**)&pCtxh,   g_ctxh);
    cudaGetSymbolAddress((void**)&pAtt,    g_att);
    cudaGetSymbolAddress((void**)&pTh,     g_Th);
    cudaGetSymbolAddress((void**)&pNSh,    g_NSh);
    cudaGetSymbolAddress((void**)&pPart,   g_part);

    cudaFuncSetAttribute(hgemm<0,0,1,1>, cudaFuncAttributeMaxDynamicSharedMemorySize, SMEM128);
    cudaFuncSetAttribute(hgemm<1,0,0,0>, cudaFuncAttributeMaxDynamicSharedMemorySize, SMEM128);
    cudaFuncSetAttribute(hgemm<1,1,0,0>, cudaFuncAttributeMaxDynamicSharedMemorySize, SMEM128);
    cudaFuncSetAttribute(hgemm<2,0,2,0>, cudaFuncAttributeMaxDynamicSharedMemorySize, SMEM128);
    cudaFuncSetAttribute(hgemm<2,0,1,0>, cudaFuncAttributeMaxDynamicSharedMemorySize, SMEM128);

    // 0) fused fp32 -> fp16 conversions (one launch, 8 segments)
    CvtArgs ca;
    ca.s[0] = inputs; ca.d[0] = pInh;
    ca.s[1] = state;  ca.d[1] = pSth;
    ca.s[2] = W_in;   ca.d[2] = pWinh;
    ca.s[3] = W_enc;  ca.d[3] = pWench;
    ca.s[4] = W_core; ca.d[4] = pWcoreh;
    ca.s[5] = W_ctx;  ca.d[5] = pWctxh;
    ca.s[6] = W_rec;  ca.d[6] = pWrech;
    ca.s[7] = W_out;  ca.d[7] = pWouth;
    cvtall_k<<<11776, 256>>>(ca);

    // 1) X partials: inputs @ W_in, split-K=2  [4096,512] K=4096 (256 CTAs)
    hgemm<0,0,1,1><<<dim3(HIN/128, BENT/128, 2), 256, SMEM128>>>(pInh, pWinh, b_in, nullptr, pPart, HIN, MDIM);
    //    combine: Xh = elu(p0+p1+b_in)
    xcomb_k<<<(BENT*HIN/4)/256, 256>>>(pPart, b_in, pXh);
    // 2) S1 = relu(state @ W_enc)          [4096,256]  K=512
    hgemm<1,0,0,0><<<dim3(HENC/128, BENT/128), 256, SMEM128>>>(pSth, pWench, b_enc, pS1h, nullptr, HENC, HSTATE);
    // 3) core = relu([cs|fs] @ W_core)     [28672,512] K=512 gathered
    hgemm<1,1,0,0><<<dim3(HCORE/128, NPAIR/128), 256, SMEM128>>>(pS1h, pWcoreh, b_core, pCoreh, nullptr, HCORE, 2*HENC);
    // 4) ctx = relu(core @ W_ctx)          [28672,256] K=512
    hgemm<1,0,0,0><<<dim3(HCTX/128, NPAIR/128), 256, SMEM128>>>(pCoreh, pWctxh, b_ctx, pCtxh, nullptr, HCTX, HCORE);
    // 5) att = sigmoid(core @ W_att)       [28672]
    att_k<<<(NPAIR * 32 + 255) / 256, 256>>>(pCoreh, W_att, b_att, pAtt);
    // 6+7) fused E-sum + pack T            [4096,1024]
    ep_k<<<BENT, 256>>>(pCtxh, pAtt, pS1h, pXh, pTh);
    // 8) new_state = sigmoid(T @ W_rec)    [4096,512]  K=1024, fp32+fp16
    hgemm<2,0,2,0><<<dim3(HSTATE/128, BENT/128), 256, SMEM128>>>(pTh, pWrech, b_rec, pNSh, new_state, HSTATE, HTOT);
    // 9) out = sigmoid(new_state @ W_out)  [4096,4096] K=512, fp32
    hgemm<2,0,1,0><<<dim3(MDIM/128, BENT/128), 256, SMEM128>>>(pNSh, pWouth, b_out, nullptr, out, MDIM, HSTATE);
}

// round 11
// speedup vs baseline: 1.5496x; 1.0246x over previous
#include <cuda_runtime.h>
#include <cuda_fp16.h>
#include <math.h>
#include <stdint.h>

// Problem dims (fixed)
#define KENT    8
#define BENT    4096
#define MDIM    4096
#define HIN     512
#define HENC    256
#define HCORE   512
#define HCTX    256
#define HSTATE  512
#define NPAIR   (BENT * (KENT - 1))   // 28672
#define HTOT    (HENC + HCTX + HIN)   // 1024

// ---- fp16 scratch (no allocation allowed) ----
__device__ __half g_inh[(size_t)BENT * MDIM];
__device__ __half g_sth[BENT * HSTATE];
__device__ __half g_Winh[MDIM * HIN];
__device__ __half g_Wench[HSTATE * HENC];
__device__ __half g_Wcoreh[2 * HENC * HCORE];
__device__ __half g_Wctxh[HCORE * HCTX];
__device__ __half g_Wrech[HTOT * HSTATE];
__device__ __half g_Wouth[HSTATE * MDIM];
__device__ __half g_Xh[BENT * HIN];
__device__ __half g_S1h[BENT * HENC];
__device__ __half g_coreh[(size_t)NPAIR * HCORE];
__device__ __half g_ctxh[(size_t)NPAIR * HCTX];
__device__ float  g_att[NPAIR];
__device__ __half g_Th[BENT * HTOT];
__device__ __half g_NSh[BENT * HSTATE];

template<int ACT>
__device__ __forceinline__ float actf(float v) {
    if (ACT == 1) return fmaxf(v, 0.0f);                  // relu
    if (ACT == 2) return 1.0f / (1.0f + expf(-v));        // sigmoid
    if (ACT == 3) return v > 0.0f ? v : expm1f(v);        // elu
    return v;
}

// ---- fused fp32->fp16 conversion over 8 fixed segments ----
struct CvtArgs { const float* s[8]; __half* d[8]; };

__global__ void __launch_bounds__(256)
cvtall_k(CvtArgs a)
{
    long long i = ((long long)blockIdx.x * 256 + threadIdx.x) * 8;
    int seg; long long off;
    if      (i < 16777216LL) { seg = 0; off = i; }
    else if (i < 18874368LL) { seg = 1; off = i - 16777216LL; }
    else if (i < 20971520LL) { seg = 2; off = i - 18874368LL; }
    else if (i < 21102592LL) { seg = 3; off = i - 20971520LL; }
    else if (i < 21364736LL) { seg = 4; off = i - 21102592LL; }
    else if (i < 21495808LL) { seg = 5; off = i - 21364736LL; }
    else if (i < 22020096LL) { seg = 6; off = i - 21495808LL; }
    else if (i < 24117248LL) { seg = 7; off = i - 22020096LL; }
    else return;
    const float* s = a.s[seg] + off;
    __half* d = a.d[seg] + off;
    float4 x = *(const float4*)s;
    float4 y = *(const float4*)(s + 4);
    __half2 h0 = __floats2half2_rn(x.x, x.y);
    __half2 h1 = __floats2half2_rn(x.z, x.w);
    __half2 h2 = __floats2half2_rn(y.x, y.y);
    __half2 h3 = __floats2half2_rn(y.z, y.w);
    uint4 o;
    o.x = *(uint32_t*)&h0; o.y = *(uint32_t*)&h1;
    o.z = *(uint32_t*)&h2; o.w = *(uint32_t*)&h3;
    *(uint4*)d = o;
}

#define STAGES 4
#define ASTR 80                       // A row: 32 fp16 + 16B pad
#define BSTR 272                      // B row: 128 fp16 + 16B pad
#define BBUF (32 * BSTR)              // 8704
#define ABUF (128 * ASTR)             // 10240
#define STGB (ABUF + BBUF)
#define SMEM128 (STAGES * STGB)       // 75776

__device__ __forceinline__ void cp16(uint32_t dst, const void* src) {
    asm volatile("cp.async.cg.shared.global [%0], [%1], 16;" :: "r"(dst), "l"(src));
}

// fp16 tensor-core GEMM body (R5-proven shape), callable with explicit (bx,by).
// 128x128 CTA tile, BK=32, 256 threads, 8 warps 2x4, warp tile 64x32.
// MODE 0: normal A. MODE 1: pair-gathered A from S1h (K = 2*HENC).
// WOUT 0: fp16 C. 1: fp32 C. 2: both.
template<int ACT, int MODE, int WOUT>
__device__ __forceinline__ void
hgemm_dev(const __half* __restrict__ A, const __half* __restrict__ B,
          const float* __restrict__ bias, __half* __restrict__ Ch,
          float* __restrict__ Cf, int N, int K, int bx, int by, char* sm)
{
    const uint32_t smb = (uint32_t)__cvta_generic_to_shared(sm);

    const int tid  = threadIdx.x;
    const int warp = tid >> 5;
    const int lane = tid & 31;
    const int row0 = by * 128;
    const int col0 = bx * 128;

    const int wm = warp >> 2, wn = warp & 3;
    const int m_base = wm * 64, n_base = wn * 32;
    const int grp = lane >> 2, tg = lane & 3;

    const int a_row = (lane & 7) + ((lane >> 3) & 1) * 8;
    const int a_kh  = (lane >> 4) * 8;
    const uint32_t aLane = (uint32_t)((m_base + a_row) * ASTR + a_kh * 2);
    const int b_k  = (lane & 7) + ((lane >> 3) & 1) * 8;
    const int b_nh = (lane >> 4) * 8;
    const uint32_t bLane = (uint32_t)(b_k * BSTR + (n_base + b_nh) * 2);

    const int arow = tid >> 1;
    const int ak16 = (tid & 1) * 16;
    const uint32_t aoff = (uint32_t)(arow * ASTR + ak16 * 2);
    size_t rcs = 0, rfs = 0;
    const __half* aBase = nullptr;
    if (MODE == 0) {
        aBase = A + (size_t)(row0 + arow) * K + ak16;
    } else {
        int p = row0 + arow;
        int b_ = p / 56, rem = p % 56;
        int ii = rem / 7, jj = rem % 7;
        int j = jj + (jj >= ii ? 1 : 0);
        rcs = (size_t)(b_ * KENT + j) * HENC;
        rfs = (size_t)(b_ * KENT + ii) * HENC;
    }
    const int brow = tid >> 3;
    const int bo16 = (tid & 7) * 16;
    const uint32_t boff = (uint32_t)(brow * BSTR + bo16 * 2);
    const __half* bBase = B + (size_t)brow * N + col0 + bo16;

    auto issue_stage = [&](int s, int kg) {
        uint32_t ab = smb + (uint32_t)s * STGB;
        uint32_t bb = ab + ABUF;
        const __half* asrc;
        if (MODE == 0) {
            asrc = aBase + kg;
        } else {
            int kk = kg + ak16;
            asrc = (kk < HENC) ? (A + rcs + kk) : (A + rfs + (kk - HENC));
        }
        cp16(ab + aoff, asrc);
        cp16(ab + aoff + 16, asrc + 8);
        const __half* bsrc = bBase + (size_t)kg * N;
        cp16(bb + boff, bsrc);
        cp16(bb + boff + 16, bsrc + 8);
    };

    float acc[4][4][4];
#pragma unroll
    for (int mt = 0; mt < 4; mt++)
#pragma unroll
        for (int nt = 0; nt < 4; nt++)
#pragma unroll
            for (int c = 0; c < 4; c++) acc[mt][nt][c] = 0.0f;

    const int nk = K >> 5;

#pragma unroll
    for (int s = 0; s < STAGES - 1; s++) {
        if (s < nk) issue_stage(s, s << 5);
        asm volatile("cp.async.commit_group;" ::: "memory");
    }

    for (int it = 0; it < nk; ++it) {
        asm volatile("cp.async.wait_group %0;" :: "n"(STAGES - 2) : "memory");
        __syncthreads();
        const int nxt = it + STAGES - 1;
        if (nxt < nk) issue_stage(nxt & (STAGES - 1), nxt << 5);
        asm volatile("cp.async.commit_group;" ::: "memory");

        const uint32_t ab = smb + (uint32_t)(it & (STAGES - 1)) * STGB + aLane;
        const uint32_t bb = smb + (uint32_t)(it & (STAGES - 1)) * STGB + ABUF + bLane;
#pragma unroll
        for (int ks = 0; ks < 2; ks++) {
            uint32_t af[4][4];
#pragma unroll
            for (int mt = 0; mt < 4; mt++) {
                uint32_t addr = ab + mt * (16 * ASTR) + ks * 32;
                asm volatile("ldmatrix.sync.aligned.m8n8.x4.shared.b16 {%0,%1,%2,%3}, [%4];"
                             : "=r"(af[mt][0]), "=r"(af[mt][1]),
                               "=r"(af[mt][2]), "=r"(af[mt][3])
                             : "r"(addr));
            }
            uint32_t bf[4][2];
#pragma unroll
            for (int nl = 0; nl < 2; nl++) {
                uint32_t addr = bb + nl * 32 + ks * (16 * BSTR);
                asm volatile("ldmatrix.sync.aligned.m8n8.x4.trans.shared.b16 {%0,%1,%2,%3}, [%4];"
                             : "=r"(bf[nl*2][0]), "=r"(bf[nl*2][1]),
                               "=r"(bf[nl*2+1][0]), "=r"(bf[nl*2+1][1])
                             : "r"(addr));
            }
#pragma unroll
            for (int mt = 0; mt < 4; mt++) {
#pragma unroll
                for (int nt = 0; nt < 4; nt++) {
                    asm("mma.sync.aligned.m16n8k16.row.col.f32.f16.f16.f32 "
                        "{%0,%1,%2,%3}, {%4,%5,%6,%7}, {%8,%9}, {%0,%1,%2,%3};"
                        : "+f"(acc[mt][nt][0]), "+f"(acc[mt][nt][1]),
                          "+f"(acc[mt][nt][2]), "+f"(acc[mt][nt][3])
                        : "r"(af[mt][0]), "r"(af[mt][1]), "r"(af[mt][2]), "r"(af[mt][3]),
                          "r"(bf[nt][0]), "r"(bf[nt][1]));
                }
            }
        }
    }

#pragma unroll
    for (int nt = 0; nt < 4; nt++) {
        int col = col0 + n_base + nt * 8 + 2 * tg;
        float2 bb2 = *(const float2*)(bias + col);
#pragma unroll
        for (int mt = 0; mt < 4; mt++) {
            int row = row0 + m_base + mt * 16 + grp;
            float v00 = actf<ACT>(acc[mt][nt][0] + bb2.x);
            float v01 = actf<ACT>(acc[mt][nt][1] + bb2.y);
            float v10 = actf<ACT>(acc[mt][nt][2] + bb2.x);
            float v11 = actf<ACT>(acc[mt][nt][3] + bb2.y);
            if (WOUT != 1) {
                __half2 h0 = __floats2half2_rn(v00, v01);
                __half2 h1 = __floats2half2_rn(v10, v11);
                *(__half2*)(Ch + (size_t)row * N + col) = h0;
                *(__half2*)(Ch + (size_t)(row + 8) * N + col) = h1;
            }
            if (WOUT != 0) {
                float2 f0 = {v00, v01}, f1 = {v10, v11};
                *(float2*)(Cf + (size_t)row * N + col) = f0;
                *(float2*)(Cf + (size_t)(row + 8) * N + col) = f1;
            }
        }
    }
}

// standalone GEMM wrapper
template<int ACT, int MODE, int WOUT>
__global__ void __launch_bounds__(256, 2)
hgemm_g(const __half* __restrict__ A, const __half* __restrict__ B,
        const float* __restrict__ bias, __half* __restrict__ Ch,
        float* __restrict__ Cf, int N, int K)
{
    extern __shared__ char sm[];
    hgemm_dev<ACT, MODE, WOUT>(A, B, bias, Ch, Cf, N, K, blockIdx.x, blockIdx.y, sm);
}

// fused: core GEMM (blocks 0..895) + X GEMM (blocks 896..1023)
// core grid: 4 col-blocks x 224 row-blocks = 896. X grid: 4 x 32 = 128.
__global__ void __launch_bounds__(256, 2)
fused_cx(const __half* __restrict__ S1, const __half* __restrict__ Wcore,
         const float* __restrict__ bcore, __half* __restrict__ coreh,
         const __half* __restrict__ inh, const __half* __restrict__ Winh,
         const float* __restrict__ bin, __half* __restrict__ Xh)
{
    extern __shared__ char sm[];
    int b = blockIdx.x;
    if (b < 896) {
        hgemm_dev<1, 1, 0>(S1, Wcore, bcore, coreh, nullptr, HCORE, 2 * HENC,
                           b & 3, b >> 2, sm);
    } else {
        b -= 896;
        hgemm_dev<3, 0, 0>(inh, Winh, bin, Xh, nullptr, HIN, MDIM,
                           b & 3, b >> 2, sm);
    }
}

// fused: ctx GEMM (blocks 0..447) + attention (blocks 448..895, 64 rows each)
__global__ void __launch_bounds__(256, 2)
fused_ca(const __half* __restrict__ core, const __half* __restrict__ Wctx,
         const float* __restrict__ bctx, __half* __restrict__ ctxh,
         const float* __restrict__ W_att, const float* __restrict__ b_att,
         float* __restrict__ att)
{
    extern __shared__ char sm[];
    int b = blockIdx.x;
    if (b < 448) {
        hgemm_dev<1, 0, 0>(core, Wctx, bctx, ctxh, nullptr, HCTX, HCORE,
                           b & 1, b >> 1, sm);
    } else {
        b -= 448;                          // 0..447, 64 rows each
        int warp = threadIdx.x >> 5;
        int lane = threadIdx.x & 31;
        int base = b * 64 + warp * 8;
        float batt = b_att[0];
#pragma unroll 1
        for (int r = 0; r < 8; r++) {
            int row = base + r;
            const __half2* p = (const __half2*)(core + (size_t)row * HCORE);
            float s = 0.0f;
#pragma unroll
            for (int k = lane; k < 256; k += 32) {
                float2 f = __half22float2(p[k]);
                s += f.x * W_att[2 * k] + f.y * W_att[2 * k + 1];
            }
#pragma unroll
            for (int o = 16; o; o >>= 1) s += __shfl_xor_sync(0xFFFFFFFFu, s, o);
            if (lane == 0) att[row] = 1.0f / (1.0f + expf(-(s + batt)));
        }
    }
}

// fused: E = sum_j att*ctx, then T = [S1 | E | X]
__global__ void __launch_bounds__(256)
ep_k(const __half* __restrict__ ctx, const float* __restrict__ att,
     const __half* __restrict__ S1, const __half* __restrict__ X,
     __half* __restrict__ T)
{
    int e = blockIdx.x;
    int t = threadIdx.x;
    float s = 0.0f;
#pragma unroll
    for (int jj = 0; jj < 7; jj++) {
        int p = e * 7 + jj;
        s += att[p] * __half2float(ctx[(size_t)p * HCTX + t]);
    }
    T[(size_t)e * HTOT + 256 + t] = __float2half(s);
    T[(size_t)e * HTOT + t]       = S1[(size_t)e * HENC + t];
    T[(size_t)e * HTOT + 512 + t] = X[(size_t)e * HIN + t];
    T[(size_t)e * HTOT + 768 + t] = X[(size_t)e * HIN + 256 + t];
}

extern "C" void kernel_launch(void* const* d_in, const int* in_sizes, int n_in,
                              void* d_out, int out_size)
{
    const float* inputs = (const float*)d_in[0];
    const float* state  = (const float*)d_in[1];
    const float* W_in   = (const float*)d_in[2];
    const float* b_in   = (const float*)d_in[3];
    const float* W_enc  = (const float*)d_in[4];
    const float* b_enc  = (const float*)d_in[5];
    const float* W_core = (const float*)d_in[6];
    const float* b_core = (const float*)d_in[7];
    const float* W_ctx  = (const float*)d_in[8];
    const float* b_ctx  = (const float*)d_in[9];
    const float* W_att  = (const float*)d_in[10];
    const float* b_att  = (const float*)d_in[11];
    const float* W_rec  = (const float*)d_in[12];
    const float* b_rec  = (const float*)d_in[13];
    const float* W_out  = (const float*)d_in[14];
    const float* b_out  = (const float*)d_in[15];

    float* out       = (float*)d_out;
    float* new_state = (float*)d_out + (size_t)BENT * MDIM;

    __half *pInh, *pSth, *pWinh, *pWench, *pWcoreh, *pWctxh, *pWrech, *pWouth;
    __half *pXh, *pS1h, *pCoreh, *pCtxh, *pTh, *pNSh;
    float  *pAtt;
    cudaGetSymbolAddress((void**)&pInh,    g_inh);
    cudaGetSymbolAddress((void**)&pSth,    g_sth);
    cudaGetSymbolAddress((void**)&pWinh,   g_Winh);
    cudaGetSymbolAddress((void**)&pWench,  g_Wench);
    cudaGetSymbolAddress((void**)&pWcoreh, g_Wcoreh);
    cudaGetSymbolAddress((void**)&pWctxh,  g_Wctxh);
    cudaGetSymbolAddress((void**)&pWrech,  g_Wrech);
    cudaGetSymbolAddress((void**)&pWouth,  g_Wouth);
    cudaGetSymbolAddress((void**)&pXh,     g_Xh);
    cudaGetSymbolAddress((void**)&pS1h,    g_S1h);
    cudaGetSymbolAddress((void**)&pCoreh,  g_coreh);
    cudaGetSymbolAddress((void**)&pCtxh,   g_ctxh);
    cudaGetSymbolAddress((void**)&pAtt,    g_att);
    cudaGetSymbolAddress((void**)&pTh,     g_Th);
    cudaGetSymbolAddress((void**)&pNSh,    g_NSh);

    cudaFuncSetAttribute(hgemm_g<1,0,0>, cudaFuncAttributeMaxDynamicSharedMemorySize, SMEM128);
    cudaFuncSetAttribute(hgemm_g<2,0,2>, cudaFuncAttributeMaxDynamicSharedMemorySize, SMEM128);
    cudaFuncSetAttribute(hgemm_g<2,0,1>, cudaFuncAttributeMaxDynamicSharedMemorySize, SMEM128);
    cudaFuncSetAttribute(fused_cx,       cudaFuncAttributeMaxDynamicSharedMemorySize, SMEM128);
    cudaFuncSetAttribute(fused_ca,       cudaFuncAttributeMaxDynamicSharedMemorySize, SMEM128);

    // 0) fused fp32 -> fp16 conversions (one launch, 8 segments)
    CvtArgs ca;
    ca.s[0] = inputs; ca.d[0] = pInh;
    ca.s[1] = state;  ca.d[1] = pSth;
    ca.s[2] = W_in;   ca.d[2] = pWinh;
    ca.s[3] = W_enc;  ca.d[3] = pWench;
    ca.s[4] = W_core; ca.d[4] = pWcoreh;
    ca.s[5] = W_ctx;  ca.d[5] = pWctxh;
    ca.s[6] = W_rec;  ca.d[6] = pWrech;
    ca.s[7] = W_out;  ca.d[7] = pWouth;
    cvtall_k<<<11776, 256>>>(ca);

    // 1) S1 = relu(state @ W_enc)          [4096,256]  K=512
    hgemm_g<1,0,0><<<dim3(HENC/128, BENT/128), 256, SMEM128>>>(pSth, pWench, b_enc, pS1h, nullptr, HENC, HSTATE);
    // 2) fused: core GEMM (896 CTAs) + X GEMM (128 CTAs)
    fused_cx<<<1024, 256, SMEM128>>>(pS1h, pWcoreh, b_core, pCoreh,
                                     pInh, pWinh, b_in, pXh);
    // 3) fused: ctx GEMM (448 CTAs) + attention (448 CTAs)
    fused_ca<<<896, 256, SMEM128>>>(pCoreh, pWctxh, b_ctx, pCtxh,
                                    W_att, b_att, pAtt);
    // 4) fused E-sum + pack T              [4096,1024]
    ep_k<<<BENT, 256>>>(pCtxh, pAtt, pS1h, pXh, pTh);
    // 5) new_state = sigmoid(T @ W_rec)    [4096,512]  K=1024, fp32+fp16
    hgemm_g<2,0,2><<<dim3(HSTATE/128, BENT/128), 256, SMEM128>>>(pTh, pWrech, b_rec, pNSh, new_state, HSTATE, HTOT);
    // 6) out = sigmoid(new_state @ W_out)  [4096,4096] K=512, fp32
    hgemm_g<2,0,1><<<dim3(MDIM/128, BENT/128), 256, SMEM128>>>(pNSh, pWouth, b_out, nullptr, out, MDIM, HSTATE);
}